// round 16
// baseline (speedup 1.0000x reference)
#include <cuda_runtime.h>
#include <cuda_fp16.h>
#include <math.h>
#include <stdint.h>

// Problem constants
#define T_TOKENS 16384
#define DDIM     1024
#define NEXP     8

// GEMM tiling: CTA 128x256, warp tile 64x64 (2x4 warp grid), BK=64
#define BM 128
#define BN 256
#define BK 64                      // fp16 elems per k-slab = 128B rows
#define LDR 72                     // 64 data + 8 pad = 144B stride (conflict-free)
#define NSLAB (DDIM / BK)          // 16
#define MAXTILES 264

// stage layout (bytes): A | B
#define A_BYTES (BM * LDR * 2)     // 18432
#define B_BYTES (BN * LDR * 2)     // 36864
#define OFF_A 0
#define OFF_B A_BYTES
#define STAGE_BYTES (A_BYTES + B_BYTES)            // 55296
#define SMEM_DYN (3 * STAGE_BYTES)                 // 165888 -> 1 CTA/SM

// ---------------- scratch (static device globals; no allocation) ------------
__device__ int    g_count[NEXP];
__device__ int    g_base[NEXP];
__device__ int    g_tok[NEXP][T_TOKENS];
__device__ int4   g_assign[T_TOKENS];
__device__ float2 g_tw[T_TOKENS];
__device__ int    g_ntiles;
__device__ int    g_te[MAXTILES];
__device__ int    g_trow[MAXTILES];

__device__ __half g_x16[T_TOKENS * DDIM];
__device__ __half g_w1[NEXP * DDIM * DDIM];
__device__ __half g_w2[NEXP * DDIM * DDIM];
__device__ __half g_H[2 * T_TOKENS * DDIM];
__device__ float  g_Y[2 * T_TOKENS * DDIM];

// ---------------- helpers ----------------------------------------------------
static __device__ __forceinline__ uint32_t smem_u32(const void* p) {
    uint32_t a;
    asm("{ .reg .u64 t; cvta.to.shared.u64 t, %1; cvt.u32.u64 %0, t; }"
        : "=r"(a) : "l"(p));
    return a;
}
static __device__ __forceinline__ void cp16(uint32_t dst, const void* src) {
    asm volatile("cp.async.cg.shared.global [%0], [%1], 16;" :: "r"(dst), "l"(src));
}
static __device__ __forceinline__ void cp_commit() {
    asm volatile("cp.async.commit_group;" ::: "memory");
}
static __device__ __forceinline__ void cp_wait1() {
    asm volatile("cp.async.wait_group 1;" ::: "memory");
}

static __device__ __forceinline__ void ldsm4(uint32_t* r, const __half* p) {
    uint32_t a = (uint32_t)__cvta_generic_to_shared(p);
    asm volatile("ldmatrix.sync.aligned.m8n8.x4.shared.b16 {%0,%1,%2,%3}, [%4];"
                 : "=r"(r[0]), "=r"(r[1]), "=r"(r[2]), "=r"(r[3])
                 : "r"(a));
}
static __device__ __forceinline__ void mma16816(float* c, const uint32_t* a, const uint32_t* b) {
    asm volatile("mma.sync.aligned.m16n8k16.row.col.f32.f16.f16.f32 "
                 "{%0,%1,%2,%3},{%4,%5,%6,%7},{%8,%9},{%0,%1,%2,%3};"
                 : "+f"(c[0]), "+f"(c[1]), "+f"(c[2]), "+f"(c[3])
                 : "r"(a[0]), "r"(a[1]), "r"(a[2]), "r"(a[3]),
                   "r"(b[0]), "r"(b[1]));
}

// ---------------- init ------------------------------------------------------
__global__ void init_counts_kernel() {
    if (threadIdx.x < NEXP) {
        g_count[threadIdx.x] = 0;
    }
}

// ---------------- fp32 -> fp16 weight conversion ------------------------------
__global__ void conv_half_kernel(const float* __restrict__ src, int which, int n4) {
    __half* dst = (which == 1) ? g_w1 : g_w2;
    int idx = blockIdx.x * blockDim.x + threadIdx.x;
    const int stride = gridDim.x * blockDim.x;
    for (; idx < n4; idx += stride) {
        float4 v = ((const float4*)src)[idx];
        __half2 h01 = __floats2half2_rn(v.x, v.y);
        __half2 h23 = __floats2half2_rn(v.z, v.w);
        uint2 hv;
        hv.x = *reinterpret_cast<uint32_t*>(&h01);
        hv.y = *reinterpret_cast<uint32_t*>(&h23);
        ((uint2*)dst)[idx] = hv;
    }
}

// ---------------- router (also emits x fp16) ----------------------------------
__global__ void router_kernel(const float* __restrict__ x,
                              const float* __restrict__ Wr) {
    __shared__ __align__(16) float sWr[NEXP * DDIM];
    for (int i = threadIdx.x; i < NEXP * DDIM; i += blockDim.x) {
        sWr[i] = Wr[i];
    }
    __syncthreads();

    const int warp = threadIdx.x >> 5;
    const int lane = threadIdx.x & 31;
    const int t = blockIdx.x * 8 + warp;

    const float4* xr = (const float4*)(x + (size_t)t * DDIM);
    const float4* wr = (const float4*)sWr;
    uint2* xh = (uint2*)(g_x16 + (size_t)t * DDIM);

    float acc[NEXP];
#pragma unroll
    for (int e = 0; e < NEXP; e++) {
        acc[e] = 0.f;
    }

    for (int i = lane; i < DDIM / 4; i += 32) {
        float4 xv = xr[i];
        {
            __half2 h01 = __floats2half2_rn(xv.x, xv.y);
            __half2 h23 = __floats2half2_rn(xv.z, xv.w);
            uint2 hv;
            hv.x = *reinterpret_cast<uint32_t*>(&h01);
            hv.y = *reinterpret_cast<uint32_t*>(&h23);
            xh[i] = hv;
        }
#pragma unroll
        for (int e = 0; e < NEXP; e++) {
            float4 wv = wr[e * (DDIM / 4) + i];
            acc[e] += xv.x * wv.x + xv.y * wv.y + xv.z * wv.z + xv.w * wv.w;
        }
    }
#pragma unroll
    for (int e = 0; e < NEXP; e++) {
#pragma unroll
        for (int off = 16; off; off >>= 1) {
            acc[e] += __shfl_xor_sync(0xffffffffu, acc[e], off);
        }
    }

    if (lane == 0) {
        int i1 = 0;
        float m1 = acc[0];
#pragma unroll
        for (int e = 1; e < NEXP; e++) {
            if (acc[e] > m1) { m1 = acc[e]; i1 = e; }
        }
        int i2 = -1;
        float m2 = -INFINITY;
#pragma unroll
        for (int e = 0; e < NEXP; e++) {
            if (e != i1 && acc[e] > m2) { m2 = acc[e]; i2 = e; }
        }

        float w1 = 1.0f / (1.0f + expf(m2 - m1));
        float w2 = 1.0f - w1;

        int p1 = atomicAdd(&g_count[i1], 1);
        g_tok[i1][p1] = t;
        int p2 = atomicAdd(&g_count[i2], 1);
        g_tok[i2][p2] = t;
        g_assign[t] = make_int4(i1, p1, i2, p2);
        g_tw[t] = make_float2(w1, w2);
    }
}

// ---------------- prefix + tile table -----------------------------------------
__global__ void prefix_kernel() {
    if (threadIdx.x == 0) {
        int s = 0;
        int nt = 0;
#pragma unroll
        for (int e = 0; e < NEXP; e++) {
            g_base[e] = s;
            const int c = g_count[e];
            const int tiles = (c + BM - 1) / BM;
            for (int i = 0; i < tiles; i++) {
                g_te[nt] = e;
                g_trow[nt] = i * BM;
                nt++;
            }
            s += c;
        }
        g_ntiles = nt;
    }
}

// ---------------- gemm building block ------------------------------------------
// warp tile 64x64: 4 A-frag ldsm4 + 4 B-frag ldsm4 -> 32 MMAs per kk
static __device__ __forceinline__ void compute_slab(
    const __half* sA, const __half* sB,
    int aLd, int bLd, float acc[4][8][4]) {
#pragma unroll
    for (int kk = 0; kk < BK; kk += 16) {
        uint32_t a[4][4];
        uint32_t b[4][4];
#pragma unroll
        for (int i = 0; i < 4; i++) {
            ldsm4(a[i], sA + aLd + i * 16 * LDR + kk);
        }
#pragma unroll
        for (int i = 0; i < 4; i++) {
            ldsm4(b[i], sB + bLd + i * 16 * LDR + kk);
        }
#pragma unroll
        for (int mt = 0; mt < 4; mt++) {
#pragma unroll
            for (int ng = 0; ng < 4; ng++) {
                mma16816(acc[mt][ng * 2 + 0], a[mt], &b[ng][0]);
                mma16816(acc[mt][ng * 2 + 1], a[mt], &b[ng][2]);
            }
        }
    }
}

// ============================================================================
// fp16 single-pass tensor-core grouped GEMM. CTA 128x256, warp tile 64x64.
// BK=64 slabs, 3-stage cp.async pipeline (compile-time rotation), 1 sync/slab.
// EPI 0: A = gathered x rows, B = W1[e], gelu(c+b1) -> g_H (fp16)
// EPI 1: A = packed H rows,   B = W2[e], raw c      -> g_Y (fp32)
// ============================================================================
template <int EPI>
__global__ void __launch_bounds__(256, 1)
gemm_mma_kernel(const float* __restrict__ bias) {
    const int tix = blockIdx.y;
    if (tix >= g_ntiles) { return; }
    const int e    = g_te[tix];
    const int row0 = g_trow[tix];
    const int cnt  = g_count[e];
    const int base = g_base[e];
    const int col0 = blockIdx.x * BN;

    extern __shared__ __align__(128) char dsmem[];
    const uint32_t sb = smem_u32(dsmem);

    const int tid  = threadIdx.x;
    const int lane = tid & 31;
    const int wid  = tid >> 5;

    // ---- cp.async assignment: cq = 16B chunk (0..7), rowq = row (0..31) -------
    const int cq   = tid & 7;
    const int rowq = tid >> 3;

    const __half* Ap;
    const __half* Bp;
    size_t aIdx[4];
    size_t bIdx[8];
    if (EPI == 0) {
        Ap = g_x16;
        Bp = g_w1;
#pragma unroll
        for (int j = 0; j < 4; j++) {
            int r = row0 + rowq + 32 * j;
            if (r >= cnt) { r = cnt - 1; }
            aIdx[j] = (size_t)g_tok[e][r] * DDIM + cq * 8;
        }
    } else {
        Ap = g_H;
        Bp = g_w2;
#pragma unroll
        for (int j = 0; j < 4; j++) {
            int r = row0 + rowq + 32 * j;
            if (r >= cnt) { r = cnt - 1; }
            aIdx[j] = (size_t)(base + r) * DDIM + cq * 8;
        }
    }
#pragma unroll
    for (int j = 0; j < 8; j++) {
        bIdx[j] = ((size_t)e * DDIM + col0 + rowq + 32 * j) * DDIM + cq * 8;
    }

    uint32_t oR[8];
#pragma unroll
    for (int j = 0; j < 8; j++) {
        oR[j] = (uint32_t)(rowq + 32 * j) * 144u + (uint32_t)cq * 16u;
    }

    const uint32_t st0 = sb;
    const uint32_t st1 = sb + STAGE_BYTES;
    const uint32_t st2 = sb + 2 * STAGE_BYTES;
    const __half* s0A = (const __half*)(dsmem + 0 * STAGE_BYTES + OFF_A);
    const __half* s0B = (const __half*)(dsmem + 0 * STAGE_BYTES + OFF_B);
    const __half* s1A = (const __half*)(dsmem + 1 * STAGE_BYTES + OFF_A);
    const __half* s1B = (const __half*)(dsmem + 1 * STAGE_BYTES + OFF_B);
    const __half* s2A = (const __half*)(dsmem + 2 * STAGE_BYTES + OFF_A);
    const __half* s2B = (const __half*)(dsmem + 2 * STAGE_BYTES + OFF_B);

    // ---- mma fragment smem offsets: 8 warps = 2 (m) x 4 (n), warp tile 64x64 ---
    const int wm = (wid & 1) * 64;
    const int wn = (wid >> 1) * 64;
    const int aLd = (wm + (lane & 15)) * LDR + ((lane >> 4) << 3);
    const int bLd = (wn + ((lane >> 4) << 3) + (lane & 7)) * LDR + (lane & 8);

    float acc[4][8][4];
#pragma unroll
    for (int i = 0; i < 4; i++) {
#pragma unroll
        for (int j = 0; j < 8; j++) {
#pragma unroll
            for (int q = 0; q < 4; q++) {
                acc[i][j][q] = 0.f;
            }
        }
    }

    auto refill = [&](uint32_t st, int k0) {
#pragma unroll
        for (int j = 0; j < 4; j++) {
            cp16(st + OFF_A + oR[j], Ap + aIdx[j] + k0);
        }
#pragma unroll
        for (int j = 0; j < 8; j++) {
            cp16(st + OFF_B + oR[j], Bp + bIdx[j] + k0);
        }
    };

    // ---- prologue: slabs 0,1 -> stages 0,1 --------------------------------------
    refill(st0, 0);
    cp_commit();
    refill(st1, BK);
    cp_commit();

    // ---- mainloop: slab j on stage j%3; refill stage (j+2)%3 with slab j+2 ------
    // 15 slabs in 5 macro-iterations of 3, + tail slab 15 (stage 0).
    for (int j = 0; j < 15; j += 3) {
        cp_wait1();
        __syncthreads();
        refill(st2, (j + 2) * BK);
        cp_commit();
        compute_slab(s0A, s0B, aLd, bLd, acc);

        cp_wait1();
        __syncthreads();
        refill(st0, (j + 3) * BK);
        cp_commit();
        compute_slab(s1A, s1B, aLd, bLd, acc);

        cp_wait1();
        __syncthreads();
        if (j + 4 < NSLAB) {
            refill(st1, (j + 4) * BK);
        }
        cp_commit();
        compute_slab(s2A, s2B, aLd, bLd, acc);
    }

    // tail: slab 15 (stage 0)
    cp_wait1();
    __syncthreads();
    compute_slab(s0A, s0B, aLd, bLd, acc);

    // ---- epilogue ----------------------------------------------------------------
    const int r0l = lane >> 2;
    const int c0l = (lane & 3) * 2;
#pragma unroll
    for (int mt = 0; mt < 4; mt++) {
#pragma unroll
        for (int nt = 0; nt < 8; nt++) {
            const int fc = col0 + wn + nt * 8 + c0l;
#pragma unroll
            for (int half = 0; half < 2; half++) {
                const int r = row0 + wm + mt * 16 + r0l + half * 8;
                if (r < cnt) {
                    float v0 = acc[mt][nt][half * 2 + 0];
                    float v1 = acc[mt][nt][half * 2 + 1];
                    if (EPI == 0) {
                        float2 bb = *(const float2*)(bias + (size_t)e * DDIM + fc);
                        v0 += bb.x;
                        v1 += bb.y;
                        v0 = 0.5f * v0 * (1.0f + erff(v0 * 0.70710678118654752f));
                        v1 = 0.5f * v1 * (1.0f + erff(v1 * 0.70710678118654752f));
                        *(__half2*)(g_H + (size_t)(base + r) * DDIM + fc) =
                            __floats2half2_rn(v0, v1);
                    } else {
                        *(float2*)(g_Y + (size_t)(base + r) * DDIM + fc) = make_float2(v0, v1);
                    }
                }
            }
        }
    }
}

// ---------------- combine: out[t] = w1*(y1+b2[e1]) + w2*(y2+b2[e2]) ----------
__global__ void combine_kernel(const float* __restrict__ b2,
                               float* __restrict__ out) {
    const int idx = blockIdx.x * blockDim.x + threadIdx.x;
    const int t = idx >> 8;
    const int c4 = idx & 255;
    int4 a = g_assign[t];
    float2 w = g_tw[t];
    const int s1 = g_base[a.x] + a.y;
    const int s2 = g_base[a.z] + a.w;
    float4 y1 = *(const float4*)(g_Y + (size_t)s1 * DDIM + c4 * 4);
    float4 y2 = *(const float4*)(g_Y + (size_t)s2 * DDIM + c4 * 4);
    float4 v1 = *(const float4*)(b2 + (size_t)a.x * DDIM + c4 * 4);
    float4 v2 = *(const float4*)(b2 + (size_t)a.z * DDIM + c4 * 4);
    float4 o;
    o.x = w.x * (y1.x + v1.x) + w.y * (y2.x + v2.x);
    o.y = w.x * (y1.y + v1.y) + w.y * (y2.y + v2.y);
    o.z = w.x * (y1.z + v1.z) + w.y * (y2.z + v2.z);
    o.w = w.x * (y1.w + v1.w) + w.y * (y2.w + v2.w);
    ((float4*)out)[idx] = o;
}

// ---------------- launch -----------------------------------------------------
extern "C" void kernel_launch(void* const* d_in, const int* in_sizes, int n_in,
                              void* d_out, int out_size) {
    const float* x  = (const float*)d_in[0];
    const float* Wr = (const float*)d_in[1];
    const float* W1 = (const float*)d_in[2];
    const float* b1 = (const float*)d_in[3];
    const float* W2 = (const float*)d_in[4];
    const float* b2 = (const float*)d_in[5];
    float* out = (float*)d_out;

    cudaFuncSetAttribute(gemm_mma_kernel<0>,
                         cudaFuncAttributeMaxDynamicSharedMemorySize, SMEM_DYN);
    cudaFuncSetAttribute(gemm_mma_kernel<1>,
                         cudaFuncAttributeMaxDynamicSharedMemorySize, SMEM_DYN);

    init_counts_kernel<<<1, 32>>>();
    router_kernel<<<T_TOKENS / 8, 256>>>(x, Wr);
    prefix_kernel<<<1, 32>>>();

    conv_half_kernel<<<2048, 256>>>(W1, 1, (NEXP * DDIM * DDIM) / 4);
    conv_half_kernel<<<2048, 256>>>(W2, 2, (NEXP * DDIM * DDIM) / 4);

    dim3 grid(DDIM / BN, MAXTILES);   // (4, 264), compacted tiles
    gemm_mma_kernel<0><<<grid, 256, SMEM_DYN>>>(b1);
    gemm_mma_kernel<1><<<grid, 256, SMEM_DYN>>>(b1);

    combine_kernel<<<(T_TOKENS * DDIM / 4) / 256, 256>>>(b2, out);
}

// round 17
// speedup vs baseline: 1.0792x; 1.0792x over previous
#include <cuda_runtime.h>
#include <cuda_fp16.h>
#include <math.h>
#include <stdint.h>

// Problem constants
#define T_TOKENS 16384
#define DDIM     1024
#define NEXP     8

// GEMM tiling: CTA 128x128, warp tile 32x64 (4x2 warp grid), BK=64
#define BM 128
#define BN 128
#define BK 64                      // fp16 elems per k-slab = 128B rows
#define LDR 72                     // 64 data + 8 pad = 144B stride (conflict-free)
#define NSLAB (DDIM / BK)          // 16
#define MAXTILES 264

// stage layout (bytes): A | B
#define A_BYTES (BM * LDR * 2)     // 18432
#define B_BYTES (BN * LDR * 2)     // 18432
#define OFF_A 0
#define OFF_B A_BYTES
#define STAGE_BYTES (A_BYTES + B_BYTES)            // 36864
#define SMEM_DYN (3 * STAGE_BYTES)                 // 110592 -> 2 CTAs/SM

// ---------------- scratch (static device globals; no allocation) ------------
__device__ int    g_count[NEXP];
__device__ int    g_base[NEXP];
__device__ int    g_tok[NEXP][T_TOKENS];
__device__ int4   g_assign[T_TOKENS];
__device__ float2 g_tw[T_TOKENS];
__device__ int    g_ntiles;
__device__ int    g_te[MAXTILES];
__device__ int    g_trow[MAXTILES];

__device__ __half g_x16[T_TOKENS * DDIM];
__device__ __half g_w1[NEXP * DDIM * DDIM];
__device__ __half g_w2[NEXP * DDIM * DDIM];
__device__ __half g_H[2 * T_TOKENS * DDIM];
__device__ __half g_Y[2 * T_TOKENS * DDIM];

// ---------------- helpers ----------------------------------------------------
static __device__ __forceinline__ uint32_t smem_u32(const void* p) {
    uint32_t a;
    asm("{ .reg .u64 t; cvta.to.shared.u64 t, %1; cvt.u32.u64 %0, t; }"
        : "=r"(a) : "l"(p));
    return a;
}
static __device__ __forceinline__ void cp16(uint32_t dst, const void* src) {
    asm volatile("cp.async.cg.shared.global [%0], [%1], 16;" :: "r"(dst), "l"(src));
}
static __device__ __forceinline__ void cp_commit() {
    asm volatile("cp.async.commit_group;" ::: "memory");
}
static __device__ __forceinline__ void cp_wait1() {
    asm volatile("cp.async.wait_group 1;" ::: "memory");
}
static __device__ __forceinline__ void cp_wait0() {
    asm volatile("cp.async.wait_group 0;" ::: "memory");
}

static __device__ __forceinline__ void ldsm4(uint32_t* r, const __half* p) {
    uint32_t a = (uint32_t)__cvta_generic_to_shared(p);
    asm volatile("ldmatrix.sync.aligned.m8n8.x4.shared.b16 {%0,%1,%2,%3}, [%4];"
                 : "=r"(r[0]), "=r"(r[1]), "=r"(r[2]), "=r"(r[3])
                 : "r"(a));
}
static __device__ __forceinline__ void mma16816(float* c, const uint32_t* a, const uint32_t* b) {
    asm volatile("mma.sync.aligned.m16n8k16.row.col.f32.f16.f16.f32 "
                 "{%0,%1,%2,%3},{%4,%5,%6,%7},{%8,%9},{%0,%1,%2,%3};"
                 : "+f"(c[0]), "+f"(c[1]), "+f"(c[2]), "+f"(c[3])
                 : "r"(a[0]), "r"(a[1]), "r"(a[2]), "r"(a[3]),
                   "r"(b[0]), "r"(b[1]));
}

// ---------------- init ------------------------------------------------------
__global__ void init_counts_kernel() {
    if (threadIdx.x < NEXP) {
        g_count[threadIdx.x] = 0;
    }
}

// ---------------- fp32 -> fp16 conversion for BOTH weight tensors -------------
__global__ void conv_weights_kernel(const float* __restrict__ W1src,
                                    const float* __restrict__ W2src, int n4) {
    int idx = blockIdx.x * blockDim.x + threadIdx.x;
    const int stride = gridDim.x * blockDim.x;
    for (; idx < 2 * n4; idx += stride) {
        const int w2sel = (idx >= n4);
        const int k = w2sel ? (idx - n4) : idx;
        const float4 v = w2sel ? ((const float4*)W2src)[k] : ((const float4*)W1src)[k];
        __half2 h01 = __floats2half2_rn(v.x, v.y);
        __half2 h23 = __floats2half2_rn(v.z, v.w);
        uint2 hv;
        hv.x = *reinterpret_cast<uint32_t*>(&h01);
        hv.y = *reinterpret_cast<uint32_t*>(&h23);
        if (w2sel) {
            ((uint2*)g_w2)[k] = hv;
        } else {
            ((uint2*)g_w1)[k] = hv;
        }
    }
}

// ---------------- router (also emits x fp16) ----------------------------------
__global__ void router_kernel(const float* __restrict__ x,
                              const float* __restrict__ Wr) {
    __shared__ __align__(16) float sWr[NEXP * DDIM];
    for (int i = threadIdx.x; i < NEXP * DDIM; i += blockDim.x) {
        sWr[i] = Wr[i];
    }
    __syncthreads();

    const int warp = threadIdx.x >> 5;
    const int lane = threadIdx.x & 31;
    const int t = blockIdx.x * 8 + warp;

    const float4* xr = (const float4*)(x + (size_t)t * DDIM);
    const float4* wr = (const float4*)sWr;
    uint2* xh = (uint2*)(g_x16 + (size_t)t * DDIM);

    float acc[NEXP];
#pragma unroll
    for (int e = 0; e < NEXP; e++) {
        acc[e] = 0.f;
    }

    for (int i = lane; i < DDIM / 4; i += 32) {
        float4 xv = xr[i];
        {
            __half2 h01 = __floats2half2_rn(xv.x, xv.y);
            __half2 h23 = __floats2half2_rn(xv.z, xv.w);
            uint2 hv;
            hv.x = *reinterpret_cast<uint32_t*>(&h01);
            hv.y = *reinterpret_cast<uint32_t*>(&h23);
            xh[i] = hv;
        }
#pragma unroll
        for (int e = 0; e < NEXP; e++) {
            float4 wv = wr[e * (DDIM / 4) + i];
            acc[e] += xv.x * wv.x + xv.y * wv.y + xv.z * wv.z + xv.w * wv.w;
        }
    }
#pragma unroll
    for (int e = 0; e < NEXP; e++) {
#pragma unroll
        for (int off = 16; off; off >>= 1) {
            acc[e] += __shfl_xor_sync(0xffffffffu, acc[e], off);
        }
    }

    if (lane == 0) {
        int i1 = 0;
        float m1 = acc[0];
#pragma unroll
        for (int e = 1; e < NEXP; e++) {
            if (acc[e] > m1) { m1 = acc[e]; i1 = e; }
        }
        int i2 = -1;
        float m2 = -INFINITY;
#pragma unroll
        for (int e = 0; e < NEXP; e++) {
            if (e != i1 && acc[e] > m2) { m2 = acc[e]; i2 = e; }
        }

        float w1 = 1.0f / (1.0f + expf(m2 - m1));
        float w2 = 1.0f - w1;

        int p1 = atomicAdd(&g_count[i1], 1);
        g_tok[i1][p1] = t;
        int p2 = atomicAdd(&g_count[i2], 1);
        g_tok[i2][p2] = t;
        g_assign[t] = make_int4(i1, p1, i2, p2);
        g_tw[t] = make_float2(w1, w2);
    }
}

// ---------------- prefix + tile table -----------------------------------------
__global__ void prefix_kernel() {
    if (threadIdx.x == 0) {
        int s = 0;
        int nt = 0;
#pragma unroll
        for (int e = 0; e < NEXP; e++) {
            g_base[e] = s;
            const int c = g_count[e];
            const int tiles = (c + BM - 1) / BM;
            for (int i = 0; i < tiles; i++) {
                g_te[nt] = e;
                g_trow[nt] = i * BM;
                nt++;
            }
            s += c;
        }
        g_ntiles = nt;
    }
}

// ---------------- gemm building block ------------------------------------------
// warp tile 32x64: 2 A-frag ldsm4 + 4 B-frag ldsm4 -> 16 MMAs per kk
static __device__ __forceinline__ void compute_slab(
    const __half* sA, const __half* sB,
    int aLd, int bLd, float acc[2][8][4]) {
#pragma unroll
    for (int kk = 0; kk < BK; kk += 16) {
        uint32_t a0[4];
        uint32_t a1[4];
        uint32_t b0[4];
        uint32_t b1[4];
        uint32_t b2[4];
        uint32_t b3[4];
        ldsm4(a0, sA + aLd + kk);
        ldsm4(a1, sA + aLd + 16 * LDR + kk);
        ldsm4(b0, sB + bLd + kk);
        ldsm4(b1, sB + bLd + 16 * LDR + kk);
        ldsm4(b2, sB + bLd + 32 * LDR + kk);
        ldsm4(b3, sB + bLd + 48 * LDR + kk);

        mma16816(acc[0][0], a0, &b0[0]);
        mma16816(acc[0][1], a0, &b0[2]);
        mma16816(acc[0][2], a0, &b1[0]);
        mma16816(acc[0][3], a0, &b1[2]);
        mma16816(acc[0][4], a0, &b2[0]);
        mma16816(acc[0][5], a0, &b2[2]);
        mma16816(acc[0][6], a0, &b3[0]);
        mma16816(acc[0][7], a0, &b3[2]);
        mma16816(acc[1][0], a1, &b0[0]);
        mma16816(acc[1][1], a1, &b0[2]);
        mma16816(acc[1][2], a1, &b1[0]);
        mma16816(acc[1][3], a1, &b1[2]);
        mma16816(acc[1][4], a1, &b2[0]);
        mma16816(acc[1][5], a1, &b2[2]);
        mma16816(acc[1][6], a1, &b3[0]);
        mma16816(acc[1][7], a1, &b3[2]);
    }
}

// ============================================================================
// fp16 single-pass tensor-core grouped GEMM. CTA 128x128 (2 CTAs/SM),
// 3-stage cp.async pipeline with compile-time rotation, ONE sync per slab.
// EPI 0: A = gathered x rows, B = W1[e], gelu(c+b1) -> g_H (fp16)
// EPI 1: A = packed H rows,   B = W2[e], raw c      -> g_Y (fp16)
// ============================================================================
template <int EPI>
__global__ void __launch_bounds__(256, 2)
gemm_mma_kernel(const float* __restrict__ bias) {
    const int tix = blockIdx.y;
    if (tix >= g_ntiles) { return; }
    const int e    = g_te[tix];
    const int row0 = g_trow[tix];
    const int cnt  = g_count[e];
    const int base = g_base[e];
    const int col0 = blockIdx.x * BN;

    extern __shared__ __align__(128) char dsmem[];
    const uint32_t sb = smem_u32(dsmem);

    const int tid  = threadIdx.x;
    const int lane = tid & 31;
    const int wid  = tid >> 5;

    // ---- cp.async assignment: cq = 16B chunk (0..7), rowq = row (0..31) -------
    const int cq   = tid & 7;
    const int rowq = tid >> 3;

    const __half* Ap;
    const __half* Bp;
    size_t aIdx[4];
    size_t bIdx[4];
    if (EPI == 0) {
        Ap = g_x16;
        Bp = g_w1;
#pragma unroll
        for (int j = 0; j < 4; j++) {
            int r = row0 + rowq + 32 * j;
            if (r >= cnt) { r = cnt - 1; }
            aIdx[j] = (size_t)g_tok[e][r] * DDIM + cq * 8;
        }
    } else {
        Ap = g_H;
        Bp = g_w2;
#pragma unroll
        for (int j = 0; j < 4; j++) {
            int r = row0 + rowq + 32 * j;
            if (r >= cnt) { r = cnt - 1; }
            aIdx[j] = (size_t)(base + r) * DDIM + cq * 8;
        }
    }
#pragma unroll
    for (int j = 0; j < 4; j++) {
        bIdx[j] = ((size_t)e * DDIM + col0 + rowq + 32 * j) * DDIM + cq * 8;
    }

    uint32_t oR[4];
#pragma unroll
    for (int j = 0; j < 4; j++) {
        oR[j] = (uint32_t)(rowq + 32 * j) * 144u + (uint32_t)cq * 16u;
    }

    const uint32_t st0 = sb;
    const uint32_t st1 = sb + STAGE_BYTES;
    const uint32_t st2 = sb + 2 * STAGE_BYTES;
    const __half* s0A = (const __half*)(dsmem + 0 * STAGE_BYTES + OFF_A);
    const __half* s0B = (const __half*)(dsmem + 0 * STAGE_BYTES + OFF_B);
    const __half* s1A = (const __half*)(dsmem + 1 * STAGE_BYTES + OFF_A);
    const __half* s1B = (const __half*)(dsmem + 1 * STAGE_BYTES + OFF_B);
    const __half* s2A = (const __half*)(dsmem + 2 * STAGE_BYTES + OFF_A);
    const __half* s2B = (const __half*)(dsmem + 2 * STAGE_BYTES + OFF_B);

    // ---- mma fragment smem offsets: 8 warps = 4 (m) x 2 (n), warp tile 32x64 ---
    const int wm = (wid & 3) * 32;
    const int wn = (wid >> 2) * 64;
    const int aLd = (wm + (lane & 15)) * LDR + ((lane >> 4) << 3);
    const int bLd = (wn + ((lane >> 4) << 3) + (lane & 7)) * LDR + (lane & 8);

    float acc[2][8][4];
#pragma unroll
    for (int i = 0; i < 2; i++) {
#pragma unroll
        for (int j = 0; j < 8; j++) {
#pragma unroll
            for (int q = 0; q < 4; q++) {
                acc[i][j][q] = 0.f;
            }
        }
    }

    auto refill = [&](uint32_t st, int k0) {
#pragma unroll
        for (int j = 0; j < 4; j++) {
            cp16(st + OFF_A + oR[j], Ap + aIdx[j] + k0);
        }
#pragma unroll
        for (int j = 0; j < 4; j++) {
            cp16(st + OFF_B + oR[j], Bp + bIdx[j] + k0);
        }
    };

    // ---- prologue: slabs 0,1 -> stages 0,1 --------------------------------------
    refill(st0, 0);
    cp_commit();
    refill(st1, BK);
    cp_commit();

    // ---- mainloop: slab j on stage j%3; refill stage (j+2)%3 with slab j+2 ------
    for (int j = 0; j < 15; j += 3) {
        cp_wait1();
        __syncthreads();
        refill(st2, (j + 2) * BK);
        cp_commit();
        compute_slab(s0A, s0B, aLd, bLd, acc);

        cp_wait1();
        __syncthreads();
        refill(st0, (j + 3) * BK);
        cp_commit();
        compute_slab(s1A, s1B, aLd, bLd, acc);

        cp_wait1();
        __syncthreads();
        if (j + 4 < NSLAB) {
            refill(st1, (j + 4) * BK);
        }
        cp_commit();
        compute_slab(s2A, s2B, aLd, bLd, acc);
    }

    // tail: slab 15 (stage 0)
    cp_wait0();
    __syncthreads();
    compute_slab(s0A, s0B, aLd, bLd, acc);

    // ---- epilogue ----------------------------------------------------------------
    const int r0l = lane >> 2;
    const int c0l = (lane & 3) * 2;
#pragma unroll
    for (int mt = 0; mt < 2; mt++) {
#pragma unroll
        for (int nt = 0; nt < 8; nt++) {
            const int fc = col0 + wn + nt * 8 + c0l;
#pragma unroll
            for (int half = 0; half < 2; half++) {
                const int r = row0 + wm + mt * 16 + r0l + half * 8;
                if (r < cnt) {
                    float v0 = acc[mt][nt][half * 2 + 0];
                    float v1 = acc[mt][nt][half * 2 + 1];
                    if (EPI == 0) {
                        float2 bb = *(const float2*)(bias + (size_t)e * DDIM + fc);
                        v0 += bb.x;
                        v1 += bb.y;
                        v0 = 0.5f * v0 * (1.0f + erff(v0 * 0.70710678118654752f));
                        v1 = 0.5f * v1 * (1.0f + erff(v1 * 0.70710678118654752f));
                        *(__half2*)(g_H + (size_t)(base + r) * DDIM + fc) =
                            __floats2half2_rn(v0, v1);
                    } else {
                        *(__half2*)(g_Y + (size_t)(base + r) * DDIM + fc) =
                            __floats2half2_rn(v0, v1);
                    }
                }
            }
        }
    }
}

// ---------------- combine: out[t] = w1*(y1+b2[e1]) + w2*(y2+b2[e2]) ----------
__global__ void combine_kernel(const float* __restrict__ b2,
                               float* __restrict__ out) {
    const int idx = blockIdx.x * blockDim.x + threadIdx.x;
    const int t = idx >> 8;
    const int c4 = idx & 255;
    int4 a = g_assign[t];
    float2 w = g_tw[t];
    const int s1 = g_base[a.x] + a.y;
    const int s2 = g_base[a.z] + a.w;
    uint2 y1r = *(const uint2*)(g_Y + (size_t)s1 * DDIM + c4 * 4);
    uint2 y2r = *(const uint2*)(g_Y + (size_t)s2 * DDIM + c4 * 4);
    float4 v1 = *(const float4*)(b2 + (size_t)a.x * DDIM + c4 * 4);
    float4 v2 = *(const float4*)(b2 + (size_t)a.z * DDIM + c4 * 4);
    float2 y1a = __half22float2(*reinterpret_cast<__half2*>(&y1r.x));
    float2 y1b = __half22float2(*reinterpret_cast<__half2*>(&y1r.y));
    float2 y2a = __half22float2(*reinterpret_cast<__half2*>(&y2r.x));
    float2 y2b = __half22float2(*reinterpret_cast<__half2*>(&y2r.y));
    float4 o;
    o.x = w.x * (y1a.x + v1.x) + w.y * (y2a.x + v2.x);
    o.y = w.x * (y1a.y + v1.y) + w.y * (y2a.y + v2.y);
    o.z = w.x * (y1b.x + v1.z) + w.y * (y2b.x + v2.z);
    o.w = w.x * (y1b.y + v1.w) + w.y * (y2b.y + v2.w);
    ((float4*)out)[idx] = o;
}

// ---------------- launch -----------------------------------------------------
extern "C" void kernel_launch(void* const* d_in, const int* in_sizes, int n_in,
                              void* d_out, int out_size) {
    const float* x  = (const float*)d_in[0];
    const float* Wr = (const float*)d_in[1];
    const float* W1 = (const float*)d_in[2];
    const float* b1 = (const float*)d_in[3];
    const float* W2 = (const float*)d_in[4];
    const float* b2 = (const float*)d_in[5];
    float* out = (float*)d_out;

    cudaFuncSetAttribute(gemm_mma_kernel<0>,
                         cudaFuncAttributeMaxDynamicSharedMemorySize, SMEM_DYN);
    cudaFuncSetAttribute(gemm_mma_kernel<1>,
                         cudaFuncAttributeMaxDynamicSharedMemorySize, SMEM_DYN);

    init_counts_kernel<<<1, 32>>>();
    router_kernel<<<T_TOKENS / 8, 256>>>(x, Wr);
    prefix_kernel<<<1, 32>>>();

    conv_weights_kernel<<<4096, 256>>>(W1, W2, (NEXP * DDIM * DDIM) / 4);

    dim3 grid(DDIM / BN, MAXTILES);   // (8, 264), compacted tiles
    gemm_mma_kernel<0><<<grid, 256, SMEM_DYN>>>(b1);
    gemm_mma_kernel<1><<<grid, 256, SMEM_DYN>>>(b1);

    combine_kernel<<<(T_TOKENS * DDIM / 4) / 256, 256>>>(b2, out);
}